// round 6
// baseline (speedup 1.0000x reference)
#include <cuda_runtime.h>
#include <cuda_bf16.h>
#include <cstdint>
#include <cstddef>

// Problem dims (fixed)
#define NROWS 4096
#define MCOLS 4096
#define DDIM  1024

// ---------------------------------------------------------------------------
// Scratch (__device__ globals — allocation-free contract)
// ---------------------------------------------------------------------------
__device__ __nv_bfloat16 g_Hb[(size_t)NROWS * DDIM];     // H * (1/32) in bf16
__device__ __nv_bfloat16 g_Kb[(size_t)MCOLS * DDIM];     // K in bf16
__device__ __nv_bfloat16 g_Vt[(size_t)DDIM * MCOLS];     // V^T in bf16 (K-major)
__device__ __nv_bfloat16 g_expsc[(size_t)NROWS * MCOLS]; // exp(scores) bf16
__device__ __nv_bfloat16 g_e[(size_t)NROWS * MCOLS];     // expm1(p*mask) bf16
__device__ float g_rsum[NROWS];
__device__ float g_z[NROWS];
__device__ float g_part[128 * NROWS];   // GEMM1 partial row sums (32 tiles x 4 warps)
__device__ float g_partc[128 * DDIM];   // V colsum partials (128 row-tiles)

static __device__ __forceinline__ uint32_t smem_u32(const void* p) {
    uint32_t a;
    asm("{ .reg .u64 t; cvta.to.shared.u64 t, %1; cvt.u32.u64 %0, t; }"
        : "=r"(a) : "l"(p));
    return a;
}

// ---------------------------------------------------------------------------
// mma.sync bf16 GEMM (ldmatrix + cp.async + HMMA.16816)
//   256(M) x 128(N) CTA tile, BK=64, 512 threads (16 warps, 4x4),
//   warp tile 64(M) x 32(N), 4-stage cp.async pipeline.
//   mode 2: Cb = bf16(exp(acc)); deterministic partial row sums -> part
//   mode 1: C = (Scol[col] + acc) / Zrow[row], Scol reduced from partc in-CTA
// ---------------------------------------------------------------------------
#define BM 256
#define BN 128
#define BKT 64
#define TPB 512
#define STAGES 4
#define A_BYTES 32768              // 256 x 64 bf16
#define B_BYTES 16384              // 128 x 64 bf16
#define STAGE_BYTES (A_BYTES + B_BYTES)
#define SMEM_BYTES (STAGES * STAGE_BYTES)

static __device__ __forceinline__ uint32_t sw128(uint32_t off) {
    return off ^ ((off >> 3) & 0x70);
}

static __device__ __forceinline__ void cp16(uint32_t saddr, const void* gptr) {
    asm volatile("cp.async.cg.shared.global [%0], [%1], 16;"
                 :: "r"(saddr), "l"(gptr));
}

static __device__ __forceinline__ void cp_commit() {
    asm volatile("cp.async.commit_group;");
}

template <int N>
static __device__ __forceinline__ void cp_wait() {
    asm volatile("cp.async.wait_group %0;" :: "n"(N));
}

static __device__ __forceinline__ void ldmatrix_x4(uint32_t* r, uint32_t saddr) {
    asm volatile("ldmatrix.sync.aligned.m8n8.x4.shared.b16 {%0,%1,%2,%3}, [%4];"
                 : "=r"(r[0]), "=r"(r[1]), "=r"(r[2]), "=r"(r[3]) : "r"(saddr));
}

static __device__ __forceinline__ void mma16816(float* d, const uint32_t* a,
                                                const uint32_t* b) {
    asm volatile(
        "mma.sync.aligned.m16n8k16.row.col.f32.bf16.bf16.f32 "
        "{%0,%1,%2,%3}, {%4,%5,%6,%7}, {%8,%9}, {%0,%1,%2,%3};"
        : "+f"(d[0]), "+f"(d[1]), "+f"(d[2]), "+f"(d[3])
        : "r"(a[0]), "r"(a[1]), "r"(a[2]), "r"(a[3]), "r"(b[0]), "r"(b[1]));
}

static __device__ __forceinline__ void issue_stage(
    const __nv_bfloat16* __restrict__ A, int lda, int rowBase,
    const __nv_bfloat16* __restrict__ B, int ldb, int colBase,
    int k0, uint32_t sbase, int tid) {
    uint32_t sA = sbase;
    uint32_t sB = sbase + A_BYTES;
#pragma unroll
    for (int i = 0; i < 4; i++) {      // A: 2048 16B chunks
        int l = tid + i * TPB;
        int r = l >> 3;
        int c = l & 7;
        uint32_t off = sw128((uint32_t)(r * 128 + c * 16));
        cp16(sA + off, A + (size_t)(rowBase + r) * lda + k0 + c * 8);
    }
#pragma unroll
    for (int i = 0; i < 2; i++) {      // B: 1024 16B chunks
        int l = tid + i * TPB;
        int r = l >> 3;
        int c = l & 7;
        uint32_t off = sw128((uint32_t)(r * 128 + c * 16));
        cp16(sB + off, B + (size_t)(colBase + r) * ldb + k0 + c * 8);
    }
}

__global__ void __launch_bounds__(TPB, 1)
gemm_mma(const __nv_bfloat16* __restrict__ A, const __nv_bfloat16* __restrict__ B,
         int lda, int ldb, int nIter,
         float* __restrict__ C, __nv_bfloat16* __restrict__ Cb,
         float* __restrict__ part, int ldc,
         const float* __restrict__ ScolPart, const float* __restrict__ Zrow,
         int mode) {
    extern __shared__ __align__(1024) char smem[];
    uint32_t sb = smem_u32(smem);
    int tid = threadIdx.x;
    int wid = tid >> 5, lane = tid & 31;
    int wm = wid >> 2, wn = wid & 3;        // 4x4 warp grid, warp = 64m x 32n
    int rowBase = blockIdx.y * BM;
    int colBase = blockIdx.x * BN;

#pragma unroll
    for (int s = 0; s < STAGES - 1; s++) {
        issue_stage(A, lda, rowBase, B, ldb, colBase, s * BKT,
                    sb + s * STAGE_BYTES, tid);
        cp_commit();
    }

    float acc[4][4][4];
#pragma unroll
    for (int i = 0; i < 4; i++)
#pragma unroll
        for (int j = 0; j < 4; j++)
#pragma unroll
            for (int k = 0; k < 4; k++) acc[i][j][k] = 0.f;

    int arow = wm * 64 + (lane & 15);
    int acolb = (lane >> 4) << 4;
    int brow = wn * 32 + ((lane >> 4) << 3) + (lane & 7);
    int bcolb = ((lane >> 3) & 1) << 4;

    int stage = 0;
    for (int it = 0; it < nIter; ++it) {
        cp_wait<STAGES - 2>();
        __syncthreads();
        uint32_t baseA = sb + stage * STAGE_BYTES;
        uint32_t baseB = baseA + A_BYTES;

#pragma unroll
        for (int ks = 0; ks < 4; ks++) {
            uint32_t af[4][4];
#pragma unroll
            for (int mi = 0; mi < 4; mi++) {
                uint32_t off = sw128((uint32_t)((arow + mi * 16) * 128 + ks * 32 + acolb));
                ldmatrix_x4(af[mi], baseA + off);
            }
            uint32_t bf[2][4];
#pragma unroll
            for (int ni = 0; ni < 2; ni++) {
                uint32_t off = sw128((uint32_t)((brow + ni * 16) * 128 + ks * 32 + bcolb));
                ldmatrix_x4(bf[ni], baseB + off);
            }
#pragma unroll
            for (int mi = 0; mi < 4; mi++)
#pragma unroll
                for (int ni = 0; ni < 2; ni++) {
                    mma16816(acc[mi][2 * ni], af[mi], &bf[ni][0]);
                    mma16816(acc[mi][2 * ni + 1], af[mi], &bf[ni][2]);
                }
        }

        int nxt = it + STAGES - 1;
        if (nxt < nIter) {
            issue_stage(A, lda, rowBase, B, ldb, colBase, nxt * BKT,
                        sb + ((nxt % STAGES) * STAGE_BYTES), tid);
        }
        cp_commit();
        stage = (stage + 1 == STAGES) ? 0 : stage + 1;
    }

    int mrow = rowBase + wm * 64 + (lane >> 2);
    int ncol = colBase + wn * 32 + 2 * (lane & 3);

    if (mode == 2) {
        // expsc = bf16(exp(acc)); deterministic partial row sums.
#pragma unroll
        for (int mi = 0; mi < 4; mi++) {
            int m0 = mrow + mi * 16;
            float s0 = 0.f, s1 = 0.f;
#pragma unroll
            for (int nj = 0; nj < 4; nj++) {
                int n = ncol + nj * 8;
                float e00 = __expf(acc[mi][nj][0]);
                float e01 = __expf(acc[mi][nj][1]);
                float e10 = __expf(acc[mi][nj][2]);
                float e11 = __expf(acc[mi][nj][3]);
                s0 += e00 + e01;
                s1 += e10 + e11;
                *reinterpret_cast<__nv_bfloat162*>(Cb + (size_t)m0 * ldc + n) =
                    __floats2bfloat162_rn(e00, e01);
                *reinterpret_cast<__nv_bfloat162*>(Cb + (size_t)(m0 + 8) * ldc + n) =
                    __floats2bfloat162_rn(e10, e11);
            }
            // fixed-order lane reduce (4 lanes share each row)
            s0 += __shfl_xor_sync(0xffffffffu, s0, 1);
            s0 += __shfl_xor_sync(0xffffffffu, s0, 2);
            s1 += __shfl_xor_sync(0xffffffffu, s1, 1);
            s1 += __shfl_xor_sync(0xffffffffu, s1, 2);
            if ((lane & 3) == 0) {
                int slot = blockIdx.x * 4 + wn;      // 32 coltiles x 4 warps = 128
                part[(size_t)slot * NROWS + m0]     = s0;
                part[(size_t)slot * NROWS + m0 + 8] = s1;
            }
        }
    } else {
        // mode 1: reduce Scol partials into smem, then out = (Scol + acc)/z
        cp_wait<0>();
        __syncthreads();
        float* sS = reinterpret_cast<float*>(smem);
        if (tid < BN) {
            float s = 0.f;
            const float* p = ScolPart + colBase + tid;
#pragma unroll 16
            for (int i = 0; i < 128; i++) s += p[(size_t)i * DDIM];
            sS[tid] = s;
        }
        __syncthreads();
#pragma unroll
        for (int mi = 0; mi < 4; mi++) {
            int m0 = mrow + mi * 16;
            float rz0 = 1.0f / Zrow[m0];
            float rz1 = 1.0f / Zrow[m0 + 8];
#pragma unroll
            for (int nj = 0; nj < 4; nj++) {
                int n = ncol + nj * 8;
                float s0 = sS[n - colBase], s1 = sS[n - colBase + 1];
                float2 v0, v1;
                v0.x = (s0 + acc[mi][nj][0]) * rz0;
                v0.y = (s1 + acc[mi][nj][1]) * rz0;
                v1.x = (s0 + acc[mi][nj][2]) * rz1;
                v1.y = (s1 + acc[mi][nj][3]) * rz1;
                *reinterpret_cast<float2*>(C + (size_t)m0 * ldc + n) = v0;
                *reinterpret_cast<float2*>(C + (size_t)(m0 + 8) * ldc + n) = v1;
            }
        }
    }
}

// ---------------------------------------------------------------------------
// Elementwise / reduction kernels
// ---------------------------------------------------------------------------
__global__ void conv_HK(const float* __restrict__ H, const float* __restrict__ K,
                        __nv_bfloat16* __restrict__ Hb, __nv_bfloat16* __restrict__ Kb) {
    const int n4 = NROWS * DDIM / 4;
    int i = blockIdx.x * blockDim.x + threadIdx.x;
    const float* src;
    __nv_bfloat16* dst;
    float scale;
    if (i < n4) { src = H; dst = Hb; scale = 1.0f / 32.0f; }
    else        { src = K; dst = Kb; scale = 1.0f; i -= n4; }
    float4 v = reinterpret_cast<const float4*>(src)[i];
    __nv_bfloat162 a = __floats2bfloat162_rn(v.x * scale, v.y * scale);
    __nv_bfloat162 b = __floats2bfloat162_rn(v.z * scale, v.w * scale);
    reinterpret_cast<__nv_bfloat162*>(dst)[2 * i] = a;
    reinterpret_cast<__nv_bfloat162*>(dst)[2 * i + 1] = b;
}

// V^T (bf16) + per-row-tile column partial sums (fused; single pass over V)
__global__ void transposeV(const float* __restrict__ V, __nv_bfloat16* __restrict__ Vt,
                           float* __restrict__ partc) {
    __shared__ float tile[32][33];
    __shared__ float red[8][32];
    int d0 = blockIdx.x * 32, m0 = blockIdx.y * 32;
    int tx = threadIdx.x, ty = threadIdx.y;  // 32 x 8
#pragma unroll
    for (int j = 0; j < 32; j += 8)
        tile[ty + j][tx] = V[(size_t)(m0 + ty + j) * DDIM + d0 + tx];
    __syncthreads();
#pragma unroll
    for (int j = 0; j < 32; j += 8)
        Vt[(size_t)(d0 + ty + j) * MCOLS + m0 + tx] = __float2bfloat16_rn(tile[tx][ty + j]);
    // column partials: sum over the 32 m-rows for each d = tx
    float s = (tile[ty * 4 + 0][tx] + tile[ty * 4 + 1][tx]) +
              (tile[ty * 4 + 2][tx] + tile[ty * 4 + 3][tx]);
    red[ty][tx] = s;
    __syncthreads();
    if (ty == 0) {
        float t = 0.f;
#pragma unroll
        for (int i = 0; i < 8; i++) t += red[i][tx];
        partc[(size_t)blockIdx.y * DDIM + d0 + tx] = t;
    }
}

__global__ void reduce_rsum(const float* __restrict__ part, float* __restrict__ rsum) {
    int r = blockIdx.x * 256 + threadIdx.x;
    float s0 = 0.f, s1 = 0.f, s2 = 0.f, s3 = 0.f;
#pragma unroll
    for (int j = 0; j < 128; j += 4) {
        s0 += part[(size_t)j * NROWS + r];
        s1 += part[(size_t)(j + 1) * NROWS + r];
        s2 += part[(size_t)(j + 2) * NROWS + r];
        s3 += part[(size_t)(j + 3) * NROWS + r];
    }
    rsum[r] = (s0 + s1) + (s2 + s3);
}

static __device__ __forceinline__ float warp_red_sum(float v) {
#pragma unroll
    for (int o = 16; o > 0; o >>= 1) v += __shfl_xor_sync(0xffffffffu, v, o);
    return v;
}

// fast expm1 for small non-negative x (here x <= ~0.05): cubic Taylor,
// abs err < x^4/24 < 7e-7 at the 1/16 guard; falls back to expm1f beyond.
static __device__ __forceinline__ float expm1_fast(float x) {
    float p = x * (1.0f + x * (0.5f + x * 0.16666667f));
    return (x > 0.0625f) ? expm1f(x) : p;
}

__global__ void build_e(const __nv_bfloat16* __restrict__ expsc,
                        const float* __restrict__ mask,
                        const float* __restrict__ rsum,
                        __nv_bfloat16* __restrict__ e, float* __restrict__ zrow) {
    __shared__ float red[8];
    int n = blockIdx.x, t = threadIdx.x;
    int wid = t >> 5, lid = t & 31;
    const __nv_bfloat162* srow =
        reinterpret_cast<const __nv_bfloat162*>(expsc + (size_t)n * MCOLS);
    const float4* mrow = reinterpret_cast<const float4*>(mask + (size_t)n * MCOLS);
    __nv_bfloat162* erow = reinterpret_cast<__nv_bfloat162*>(e + (size_t)n * MCOLS);
    float inv = 1.0f / rsum[n];
    float z = 0.f;
#pragma unroll
    for (int i = 0; i < 4; i++) {
        int idx = t + i * 256;
        float4 m = mrow[idx];
        __nv_bfloat162 p0 = srow[2 * idx];
        __nv_bfloat162 p1 = srow[2 * idx + 1];
        float e0 = expm1_fast(__low2float(p0)  * inv * m.x);
        float e1 = expm1_fast(__high2float(p0) * inv * m.y);
        float e2 = expm1_fast(__low2float(p1)  * inv * m.z);
        float e3 = expm1_fast(__high2float(p1) * inv * m.w);
        z += (e0 + e1) + (e2 + e3);
        erow[idx * 2] = __floats2bfloat162_rn(e0, e1);
        erow[idx * 2 + 1] = __floats2bfloat162_rn(e2, e3);
    }
    z = warp_red_sum(z);
    if (lid == 0) red[wid] = z;
    __syncthreads();
    if (t == 0) {
        float acc = 0.f;
#pragma unroll
        for (int i = 0; i < 8; i++) acc += red[i];
        zrow[n] = (float)MCOLS + acc;
    }
}

// ---------------------------------------------------------------------------
// Launch
// ---------------------------------------------------------------------------
extern "C" void kernel_launch(void* const* d_in, const int* in_sizes, int n_in,
                              void* d_out, int out_size) {
    const float* H   = (const float*)d_in[0];
    const float* K   = (const float*)d_in[1];
    const float* V   = (const float*)d_in[2];
    const float* Msk = (const float*)d_in[3];
    float* out = (float*)d_out;

    void *hb, *kb, *vt, *es, *ee, *rs, *zz, *part, *partc;
    cudaGetSymbolAddress(&hb, g_Hb);
    cudaGetSymbolAddress(&kb, g_Kb);
    cudaGetSymbolAddress(&vt, g_Vt);
    cudaGetSymbolAddress(&es, g_expsc);
    cudaGetSymbolAddress(&ee, g_e);
    cudaGetSymbolAddress(&rs, g_rsum);
    cudaGetSymbolAddress(&zz, g_z);
    cudaGetSymbolAddress(&part, g_part);
    cudaGetSymbolAddress(&partc, g_partc);

    cudaFuncSetAttribute(gemm_mma, cudaFuncAttributeMaxDynamicSharedMemorySize,
                         SMEM_BYTES);

    // Stage 0: bf16 conversions + V^T + fused colsum partials
    conv_HK<<<2 * (NROWS * DDIM / 4) / 256, 256>>>(H, K, (__nv_bfloat16*)hb,
                                                   (__nv_bfloat16*)kb);
    transposeV<<<dim3(DDIM / 32, MCOLS / 32), dim3(32, 8)>>>(V, (__nv_bfloat16*)vt,
                                                             (float*)partc);

    // Stage 1: expsc = bf16(exp(H/32 @ K^T)) + partial row sums (fused epilogue)
    gemm_mma<<<dim3(MCOLS / BN, NROWS / BM), TPB, SMEM_BYTES>>>(
        (const __nv_bfloat16*)hb, (const __nv_bfloat16*)kb, DDIM, DDIM, DDIM / BKT,
        nullptr, (__nv_bfloat16*)es, (float*)part, MCOLS, nullptr, nullptr, 2);
    reduce_rsum<<<NROWS / 256, 256>>>((const float*)part, (float*)rs);

    // Stage 2: e = expm1(softmax1 * mask) bf16; z = M + sum(e)
    build_e<<<NROWS, 256>>>((const __nv_bfloat16*)es, Msk, (const float*)rs,
                            (__nv_bfloat16*)ee, (float*)zz);

    // Stage 3: out = (colsum(V) + e @ V) / z  (Scol reduced in-epilogue)
    gemm_mma<<<dim3(DDIM / BN, NROWS / BM), TPB, SMEM_BYTES>>>(
        (const __nv_bfloat16*)ee, (const __nv_bfloat16*)vt, MCOLS, MCOLS, MCOLS / BKT,
        out, nullptr, nullptr, DDIM, (const float*)partc, (const float*)zz, 1);
}